// round 17
// baseline (speedup 1.0000x reference)
#include <cuda_runtime.h>
#include <cuda_fp16.h>
#include <cstdint>

#define MAX_N   50000
#define MAX_E   800000
#define HID     128
#define KCHUNK  32            // 24KB smem -> ~9 blocks/SM
#define ROWS_PB 32            // rows per GEMM block (4 warps x 8 rows)
#define SCAN_BS 256

typedef unsigned long long ull;

// ---------------- scratch (device globals; no allocation allowed) ----------
__device__ __align__(16) __half g_h1[MAX_N * HID];    // x @ W1 (fp16, unscaled)
__device__ __align__(16) float  g_agg1[MAX_N * HID];  // layer-1 aggregate (fp32)
__device__ __align__(16) __half g_h2[MAX_N * HID];    // (relu(agg1)@W2)*dis (fp16)
__device__ int   g_deg[MAX_N];
__device__ int   g_off[MAX_N + 1];
__device__ int   g_cnt[MAX_N];
__device__ __align__(16) int g_csr_src[MAX_E];
__device__ float g_dis[MAX_N];
__device__ int   g_bsum[512];
__device__ int   g_is_i64;

// ---------------- prep0: zero counters + dtype detect (fused) --------------
__global__ void prep0_kernel(const int* __restrict__ ei, int E, int n) {
    int i = blockIdx.x * blockDim.x + threadIdx.x;
    if (i < n) { g_deg[i] = 0; g_cnt[i] = 0; }
    if (blockIdx.x == 0) {
        __shared__ int nz;
        if (threadIdx.x == 0) nz = 0;
        __syncthreads();
        int cnt = min(E, 2048);
        for (int j = threadIdx.x; j < cnt; j += blockDim.x)
            if (ei[2 * j + 1] != 0) nz = 1;
        __syncthreads();
        if (threadIdx.x == 0) g_is_i64 = nz ? 0 : 1;
    }
}

__device__ __forceinline__ int edge_src(const int* p, int e, int E) {
    return g_is_i64 ? p[2 * e] : p[e];
}
__device__ __forceinline__ int edge_dst(const int* p, int e, int E) {
    return g_is_i64 ? p[2 * E + 2 * e] : p[E + e];
}

// ---------------- degree count ----------------------------------------------
__global__ void count_deg_kernel(const int* __restrict__ ei, int E, int n) {
    int e = blockIdx.x * blockDim.x + threadIdx.x;
    if (e < E) {
        int dst = edge_dst(ei, e, E);
        if ((unsigned)dst < (unsigned)n) atomicAdd(&g_deg[dst], 1);
    }
}

// ---------------- dis + per-block sums (scan phase A) ------------------------
__global__ void dis_scanA_kernel(int n) {
    __shared__ int s[SCAN_BS];
    int t = threadIdx.x;
    int i = blockIdx.x * SCAN_BS + t;
    int v = (i < n) ? g_deg[i] : 0;
    if (i < n) g_dis[i] = rsqrtf(1.0f + (float)v);
    s[t] = v;
    __syncthreads();
    for (int off = SCAN_BS / 2; off > 0; off >>= 1) {
        if (t < off) s[t] += s[t + off];
        __syncthreads();
    }
    if (t == 0) g_bsum[blockIdx.x] = s[0];
}

// ---------------- fused scan phase C (block offset computed redundantly) ----
__global__ void scanC_kernel(int n) {
    __shared__ int s[SCAN_BS];
    __shared__ int boff_sh;
    int t = threadIdx.x;
    int i = blockIdx.x * SCAN_BS + t;

    int part = 0;
    for (int j = t; j < blockIdx.x; j += SCAN_BS) part += g_bsum[j];
    s[t] = part;
    __syncthreads();
    for (int off = SCAN_BS / 2; off > 0; off >>= 1) {
        if (t < off) s[t] += s[t + off];
        __syncthreads();
    }
    if (t == 0) boff_sh = s[0];
    __syncthreads();
    int boff = boff_sh;
    __syncthreads();

    int v = (i < n) ? g_deg[i] : 0;
    s[t] = v;
    __syncthreads();
    #pragma unroll
    for (int off = 1; off < SCAN_BS; off <<= 1) {
        int add = (t >= off) ? s[t - off] : 0;
        __syncthreads();
        s[t] += add;
        __syncthreads();
    }
    if (i < n) g_off[i] = boff + s[t] - v;
    if (i == n - 1) g_off[n] = boff + s[t];
}

__global__ void fill_csr_kernel(const int* __restrict__ ei, int E, int n) {
    int e = blockIdx.x * blockDim.x + threadIdx.x;
    if (e >= E) return;
    int src = edge_src(ei, e, E);
    int dst = edge_dst(ei, e, E);
    if ((unsigned)src >= (unsigned)n || (unsigned)dst >= (unsigned)n) return;
    int pos = g_off[dst] + atomicAdd(&g_cnt[dst], 1);
    g_csr_src[pos] = src;
}

// ---------------- packed f32x2 FMA helper -----------------------------------
__device__ __forceinline__ void ffma2(ull& acc, ull a, ull b) {
    asm("fma.rn.f32x2 %0, %1, %2, %0;" : "+l"(acc) : "l"(a), "l"(b));
}

// ---------------- GEMM over row range [r_base, r_end), fp16 output ----------
template <bool RELU_IN, int SRC, int DST, bool PRESCALE>
__global__ void gemm_kernel(const float* __restrict__ X,
                            const float* __restrict__ W,
                            int r_base, int r_end, int K) {
    __shared__ __align__(16) float Ws[KCHUNK * HID];        // 16 KB
    __shared__ __align__(16) float2 Xs2[ROWS_PB * KCHUNK];  //  8 KB
    const float* Xp = (SRC == 0) ? X    : g_agg1;
    __half*      Hp = (DST == 0) ? g_h1 : g_h2;

    int t     = threadIdx.x;
    int lane  = t & 31;
    int warp  = t >> 5;
    int wrow0 = warp * 8;
    int r0    = r_base + blockIdx.x * ROWS_PB;

    ull acc0[8], acc1[8];
    #pragma unroll
    for (int r = 0; r < 8; r++) { acc0[r] = 0ull; acc1[r] = 0ull; }

    const ull* Wsu = reinterpret_cast<const ull*>(Ws);
    const ull* Xsu = reinterpret_cast<const ull*>(Xs2);

    for (int k0 = 0; k0 < K; k0 += KCHUNK) {
        int kc = min(KCHUNK, K - k0);
        {
            const float4* Wg = reinterpret_cast<const float4*>(W + (size_t)k0 * HID);
            float4* Wd = reinterpret_cast<float4*>(Ws);
            int nv = kc * HID / 4;
            for (int i = t; i < nv; i += blockDim.x) Wd[i] = Wg[i];
        }
        for (int i = t; i < ROWS_PB * kc; i += blockDim.x) {
            int r = i / kc, k = i % kc;
            float v = (r0 + r < r_end) ? Xp[(size_t)(r0 + r) * K + k0 + k] : 0.0f;
            if (RELU_IN) v = fmaxf(v, 0.0f);
            Xs2[r * KCHUNK + k] = make_float2(v, v);
        }
        __syncthreads();
        for (int k = 0; k < kc; k++) {
            ull w01 = Wsu[(k * HID) / 2 + lane * 2];
            ull w23 = Wsu[(k * HID) / 2 + lane * 2 + 1];
            #pragma unroll
            for (int r = 0; r < 8; r++) {
                ull xv = Xsu[(wrow0 + r) * KCHUNK + k];
                ffma2(acc0[r], xv, w01);
                ffma2(acc1[r], xv, w23);
            }
        }
        __syncthreads();
    }
    #pragma unroll
    for (int r = 0; r < 8; r++) {
        int row = r0 + wrow0 + r;
        if (row < r_end) {
            float d = PRESCALE ? g_dis[row] : 1.0f;
            float2 p0 = *reinterpret_cast<float2*>(&acc0[r]);
            float2 p1 = *reinterpret_cast<float2*>(&acc1[r]);
            __half2 lo = __floats2half2_rn(p0.x * d, p0.y * d);
            __half2 hi = __floats2half2_rn(p1.x * d, p1.y * d);
            uint2 packed;
            packed.x = *reinterpret_cast<unsigned int*>(&lo);
            packed.y = *reinterpret_cast<unsigned int*>(&hi);
            *reinterpret_cast<uint2*>(Hp + (size_t)row * HID + lane * 4) = packed;
        }
    }
}

// ---------------- CSR gather: 2 edges/warp-iter, 16 lanes/edge --------------
// One warp per node. Half-warp h (lanes 16h..16h+15) handles item i+h of the
// item list [self, csr edges...]; each lane loads uint4 = 8 fp16 columns, so
// one LDG.128 instruction moves a full 256B row per half-warp (512B/warp).
// Halves are combined with shfl_xor at the end; lanes 0-15 write the result.
template <int SRC, bool RELU_OUT, bool PRESCALED>
__global__ void gather_kernel(const float* __restrict__ b,
                              float* __restrict__ out_ptr, int n) {
    int node = (blockIdx.x * blockDim.x + threadIdx.x) >> 5;
    int lane = threadIdx.x & 31;
    if (node >= n) return;
    int half = lane >> 4;
    int coff = (lane & 15) * 8;                 // 8 fp16 columns per lane
    const __half* h   = (SRC == 0) ? g_h1   : g_h2;
    float*        agg = (SRC == 0) ? g_agg1 : out_ptr;

    float di  = g_dis[node];
    int   beg = g_off[node];
    int   T   = g_off[node + 1] - beg + 1;      // items incl. self

    float acc[8];
    #pragma unroll
    for (int k = 0; k < 8; k++) acc[k] = 0.0f;

    for (int i = 0; i < T; i += 2) {
        int item = i + half;
        if (item < T) {
            int s; float w;
            if (item == 0) {
                s = node;
                w = PRESCALED ? 1.0f : di;
            } else {
                s = g_csr_src[beg + item - 1];   // broadcast within half-warp
                w = PRESCALED ? 1.0f : g_dis[s];
            }
            uint4 raw = *reinterpret_cast<const uint4*>(h + (size_t)s * HID + coff);
            __half2 q0 = *reinterpret_cast<__half2*>(&raw.x);
            __half2 q1 = *reinterpret_cast<__half2*>(&raw.y);
            __half2 q2 = *reinterpret_cast<__half2*>(&raw.z);
            __half2 q3 = *reinterpret_cast<__half2*>(&raw.w);
            float2 f0 = __half22float2(q0);
            float2 f1 = __half22float2(q1);
            float2 f2 = __half22float2(q2);
            float2 f3 = __half22float2(q3);
            acc[0] = fmaf(f0.x, w, acc[0]); acc[1] = fmaf(f0.y, w, acc[1]);
            acc[2] = fmaf(f1.x, w, acc[2]); acc[3] = fmaf(f1.y, w, acc[3]);
            acc[4] = fmaf(f2.x, w, acc[4]); acc[5] = fmaf(f2.y, w, acc[5]);
            acc[6] = fmaf(f3.x, w, acc[6]); acc[7] = fmaf(f3.y, w, acc[7]);
        }
    }

    // combine the two halves
    #pragma unroll
    for (int k = 0; k < 8; k++)
        acc[k] += __shfl_xor_sync(0xffffffffu, acc[k], 16);

    if (half == 0) {
        const float4 b0 = *reinterpret_cast<const float4*>(b + coff);
        const float4 b1 = *reinterpret_cast<const float4*>(b + coff + 4);
        float4 o0, o1;
        o0.x = fmaf(acc[0], di, b0.x); o0.y = fmaf(acc[1], di, b0.y);
        o0.z = fmaf(acc[2], di, b0.z); o0.w = fmaf(acc[3], di, b0.w);
        o1.x = fmaf(acc[4], di, b1.x); o1.y = fmaf(acc[5], di, b1.y);
        o1.z = fmaf(acc[6], di, b1.z); o1.w = fmaf(acc[7], di, b1.w);
        if (RELU_OUT) {
            o0.x = fmaxf(o0.x, 0.f); o0.y = fmaxf(o0.y, 0.f);
            o0.z = fmaxf(o0.z, 0.f); o0.w = fmaxf(o0.w, 0.f);
            o1.x = fmaxf(o1.x, 0.f); o1.y = fmaxf(o1.y, 0.f);
            o1.z = fmaxf(o1.z, 0.f); o1.w = fmaxf(o1.w, 0.f);
        }
        float* dst = agg + (size_t)node * HID + coff;
        *reinterpret_cast<float4*>(dst)     = o0;
        *reinterpret_cast<float4*>(dst + 4) = o1;
    }
}

// ---------------- tuple tail ------------------------------------------------
__global__ void cast_ei_kernel(const int* __restrict__ ei,
                               float* __restrict__ o, int E) {
    int i = blockIdx.x * blockDim.x + threadIdx.x;
    if (i >= 2 * E) return;
    int v = (i < E) ? edge_src(ei, i, E) : edge_dst(ei, i - E, E);
    o[i] = (float)v;
}

__global__ void copy_words_kernel(const unsigned int* __restrict__ s,
                                  unsigned int* __restrict__ d, int total) {
    int i = blockIdx.x * blockDim.x + threadIdx.x;
    if (i < total) d[i] = s[i];
}

// ---------------- static side-stream (created once; no device mem) ---------
static cudaStream_t g_s2 = nullptr;
static cudaEvent_t  g_evDet = nullptr;   // prep0 done (dtype flag ready)
static cudaEvent_t  g_evM1  = nullptr;   // gemm1 done
static cudaEvent_t  g_evS2  = nullptr;   // side stream fully done (tail)
static int          g_stream_init = 0;

// ---------------------------------------------------------------------------
extern "C" void kernel_launch(void* const* d_in, const int* in_sizes, int n_in,
                              void* d_out, int out_size) {
    const float* x  = (const float*)d_in[0];
    const int*   ei = (const int*)d_in[1];
    const float* W1 = (const float*)d_in[2];
    const float* b1 = (const float*)d_in[3];
    const float* W2 = (const float*)d_in[4];
    const float* b2 = (const float*)d_in[5];
    float* out = (float*)d_out;

    const int hid = in_sizes[3];                 // 128
    const int K1  = in_sizes[2] / hid;           // 89
    const int n   = in_sizes[0] / K1;            // 50000
    const int E   = in_sizes[1] / 2;             // 800000
    const int NH  = n * hid;

    if (!g_stream_init) {
        g_stream_init = 1;
        if (cudaStreamCreateWithFlags(&g_s2, cudaStreamNonBlocking) != cudaSuccess)
            g_s2 = nullptr;
        if (g_s2) {
            cudaEventCreateWithFlags(&g_evDet, cudaEventDisableTiming);
            cudaEventCreateWithFlags(&g_evM1,  cudaEventDisableTiming);
            cudaEventCreateWithFlags(&g_evS2,  cudaEventDisableTiming);
        }
    }
    const bool fork = (g_s2 != nullptr);
    cudaStream_t sA = 0;
    cudaStream_t sB = fork ? g_s2 : (cudaStream_t)0;

    const int scan_blocks = (n + SCAN_BS - 1) / SCAN_BS;
    const int gemm_blocks = (n + ROWS_PB - 1) / ROWS_PB;
    const int gath_blocks = (int)(((long long)n * 32 + 255) / 256);
    const int rem = out_size - NH;

    // ---- prep0 (zero + dtype detect) ----
    prep0_kernel<<<(n + 255) / 256, 256, 0, sA>>>(ei, E, n);
    if (fork) { cudaEventRecord(g_evDet, sA); cudaStreamWaitEvent(sB, g_evDet, 0); }

    // ---- side stream: GEMM1 (independent of prep) then tuple tail ----
    gemm_kernel<false, 0, 0, false><<<gemm_blocks, 128, 0, sB>>>(x, W1, 0, n, K1);
    if (fork) cudaEventRecord(g_evM1, sB);
    if (rem == 2 * E) {
        cast_ei_kernel<<<(2 * E + 255) / 256, 256, 0, sB>>>(ei, out + NH, E);
    } else if (rem == 4 * E) {
        copy_words_kernel<<<(rem + 255) / 256, 256, 0, sB>>>(
            (const unsigned int*)ei, (unsigned int*)(out + NH), rem);
    }
    if (fork) cudaEventRecord(g_evS2, sB);

    // ---- main stream: degree / dis / fused scan / CSR fill ----
    count_deg_kernel<<<(E + 255) / 256, 256, 0, sA>>>(ei, E, n);
    dis_scanA_kernel<<<scan_blocks, SCAN_BS, 0, sA>>>(n);
    scanC_kernel<<<scan_blocks, SCAN_BS, 0, sA>>>(n);
    fill_csr_kernel<<<(E + 255) / 256, 256, 0, sA>>>(ei, E, n);

    // ---- join gemm1 only (tail keeps running on sB), then serial chain ----
    if (fork) cudaStreamWaitEvent(sA, g_evM1, 0);

    gather_kernel<0, false, false><<<gath_blocks, 256, 0, sA>>>(b1, out, n);
    gemm_kernel<true, 1, 1, true><<<gemm_blocks, 128, 0, sA>>>(nullptr, W2, 0, n, hid);
    gather_kernel<1, true, true><<<gath_blocks, 256, 0, sA>>>(b2, out, n);

    // ---- final join: tail must be complete before graph end ----
    if (fork) cudaStreamWaitEvent(sA, g_evS2, 0);
}